// round 1
// baseline (speedup 1.0000x reference)
#include <cuda_runtime.h>

#define NB   512
#define GH   30
#define GW   30
#define NN   900
#define HID  128
#define OUTD 64
#define ROWS 32
#define NTILES 29   // ceil(900/32)

// Ping-pong activation buffers (scratch; __device__ globals per allocation rules)
__device__ float g_X0[(size_t)NB * NN * HID];
__device__ float g_X1[(size_t)NB * NN * HID];

__device__ __forceinline__ float dinv_rc(int rp, int cp) {
    int d = 1 + (rp > 0) + (rp < GH - 1) + (cp > 0) + (cp < GW - 1);
    return rsqrtf((float)d);
}

__device__ __forceinline__ float f4get(const float4& v, int i) {
    return i == 0 ? v.x : i == 1 ? v.y : i == 2 ? v.z : v.w;
}

// ---------------------------------------------------------------------------
// x0 = relu(onehot(color)@Win + pr*Win[10] + pc*Win[11] + bin)
// ---------------------------------------------------------------------------
__global__ __launch_bounds__(256) void encode_kernel(
    const int* __restrict__ grids, const float* __restrict__ Win,
    const float* __restrict__ bin)
{
    long long idx = (long long)blockIdx.x * 256 + threadIdx.x; // over NB*NN*32
    if (idx >= (long long)NB * NN * 32) return;
    int cg = (int)(idx & 31);
    long long bn = idx >> 5;
    int n = (int)(bn % NN);
    int color = grids[bn];
    float pr = (float)(n / GW) * (1.0f / (GH - 1));
    float pc = (float)(n % GW) * (1.0f / (GW - 1));
    const float4* W4 = (const float4*)Win;
    float4 wc = W4[color * 32 + cg];
    float4 wr = W4[10 * 32 + cg];
    float4 wp = W4[11 * 32 + cg];
    float4 bb = ((const float4*)bin)[cg];
    float4 o;
    o.x = fmaxf(fmaf(pc, wp.x, fmaf(pr, wr.x, wc.x + bb.x)), 0.0f);
    o.y = fmaxf(fmaf(pc, wp.y, fmaf(pr, wr.y, wc.y + bb.y)), 0.0f);
    o.z = fmaxf(fmaf(pc, wp.z, fmaf(pr, wr.z, wc.z + bb.z)), 0.0f);
    o.w = fmaxf(fmaf(pc, wp.w, fmaf(pr, wr.w, wc.w + bb.w)), 0.0f);
    ((float4*)g_X0)[idx] = o;
}

// ---------------------------------------------------------------------------
// One GCN layer, fused:  y = A_hat @ x  (stencil)  ->  z = y@Wg + bg
//                        x_new = relu(LN(z)*gamma+beta) + x
// CTA = (batch, 32-node tile). flip selects ping-pong direction.
// smem: Ws[128][128] (64KB) + Ys[32][128] (16KB)
// ---------------------------------------------------------------------------
__global__ __launch_bounds__(256, 2) void layer_kernel(
    int flip,
    const float* __restrict__ Wg, const float* __restrict__ bg,
    const float* __restrict__ gamma, const float* __restrict__ beta)
{
    extern __shared__ float sm[];
    float* Ws = sm;                 // [128][128]
    float* Ys = sm + HID * HID;     // [32][128]

    const float* Xin  = flip ? g_X1 : g_X0;
    float*       Xout = flip ? g_X0 : g_X1;

    const int tid  = threadIdx.x;
    const int b    = blockIdx.x / NTILES;
    const int tile = blockIdx.x % NTILES;
    const int base = tile * ROWS;
    const int nrows = min(ROWS, NN - base);
    const float* Xb = Xin + (size_t)b * NN * HID;
    float*       Xob = Xout + (size_t)b * NN * HID;

    // --- load Wg into smem (coalesced float4) ---
    {
        const float4* src = (const float4*)Wg;
        float4* dst = (float4*)Ws;
        #pragma unroll
        for (int i = 0; i < 16; i++) dst[tid + 256 * i] = src[tid + 256 * i];
    }

    // --- stencil: Ys[r][:] = sum_u coef(u,v) * x[u][:] ---
    #pragma unroll
    for (int s = 0; s < 4; s++) {
        int idx = tid + 256 * s;          // r*32 + cg
        int r = idx >> 5;
        int cg = idx & 31;
        if (r < nrows) {
            int v = base + r;
            int rp = v / GW;
            int cp = v - rp * GW;
            const float4* X4 = (const float4*)Xb;
            float cv = dinv_rc(rp, cp);
            float4 xs = X4[(size_t)v * 32 + cg];
            float ax = cv * xs.x, ay = cv * xs.y, az = cv * xs.z, aw = cv * xs.w;
            if (rp > 0) {
                float cu = dinv_rc(rp - 1, cp);
                float4 t = X4[(size_t)(v - GW) * 32 + cg];
                ax = fmaf(cu, t.x, ax); ay = fmaf(cu, t.y, ay);
                az = fmaf(cu, t.z, az); aw = fmaf(cu, t.w, aw);
            }
            if (rp < GH - 1) {
                float cu = dinv_rc(rp + 1, cp);
                float4 t = X4[(size_t)(v + GW) * 32 + cg];
                ax = fmaf(cu, t.x, ax); ay = fmaf(cu, t.y, ay);
                az = fmaf(cu, t.z, az); aw = fmaf(cu, t.w, aw);
            }
            if (cp > 0) {
                float cu = dinv_rc(rp, cp - 1);
                float4 t = X4[(size_t)(v - 1) * 32 + cg];
                ax = fmaf(cu, t.x, ax); ay = fmaf(cu, t.y, ay);
                az = fmaf(cu, t.z, az); aw = fmaf(cu, t.w, aw);
            }
            if (cp < GW - 1) {
                float cu = dinv_rc(rp, cp + 1);
                float4 t = X4[(size_t)(v + 1) * 32 + cg];
                ax = fmaf(cu, t.x, ax); ay = fmaf(cu, t.y, ay);
                az = fmaf(cu, t.z, az); aw = fmaf(cu, t.w, aw);
            }
            float4 o = make_float4(cv * ax, cv * ay, cv * az, cv * aw);
            ((float4*)Ys)[idx] = o;
        }
    }
    __syncthreads();

    // --- GEMM: z[32][128] = Ys @ Ws ; thread computes 4 rows x 4 cols ---
    const int cg = tid & 31;   // col group (4 cols): lanes -> conflict-free W loads
    const int rg = tid >> 5;   // warp -> 4 rows: broadcast Y loads
    float acc[4][4];
    #pragma unroll
    for (int i = 0; i < 4; i++)
        #pragma unroll
        for (int j = 0; j < 4; j++) acc[i][j] = 0.0f;

    const float* Yp = Ys + rg * 4 * HID;
    const float* Wp = Ws + cg * 4;
    #pragma unroll 2
    for (int k0 = 0; k0 < HID; k0 += 4) {
        float4 y0 = *(const float4*)(Yp + k0);
        float4 y1 = *(const float4*)(Yp + HID + k0);
        float4 y2 = *(const float4*)(Yp + 2 * HID + k0);
        float4 y3 = *(const float4*)(Yp + 3 * HID + k0);
        #pragma unroll
        for (int kk = 0; kk < 4; kk++) {
            float4 w = *(const float4*)(Wp + (k0 + kk) * HID);
            float yr[4] = { f4get(y0, kk), f4get(y1, kk), f4get(y2, kk), f4get(y3, kk) };
            #pragma unroll
            for (int i = 0; i < 4; i++) {
                acc[i][0] = fmaf(yr[i], w.x, acc[i][0]);
                acc[i][1] = fmaf(yr[i], w.y, acc[i][1]);
                acc[i][2] = fmaf(yr[i], w.z, acc[i][2]);
                acc[i][3] = fmaf(yr[i], w.w, acc[i][3]);
            }
        }
    }
    __syncthreads();   // all reads of Ys done before overwrite

    // --- z + bias -> Ys ---
    {
        float4 bgv = ((const float4*)bg)[cg];
        #pragma unroll
        for (int i = 0; i < 4; i++) {
            float4 z = make_float4(acc[i][0] + bgv.x, acc[i][1] + bgv.y,
                                   acc[i][2] + bgv.z, acc[i][3] + bgv.w);
            ((float4*)Ys)[(rg * 4 + i) * 32 + cg] = z;
        }
    }
    __syncthreads();

    // --- LayerNorm + relu + residual: warp w handles rows w*4..w*4+3 ---
    const int lane = tid & 31;
    const int warp = tid >> 5;
    float gm0 = gamma[lane], gm1 = gamma[lane + 32], gm2 = gamma[lane + 64], gm3 = gamma[lane + 96];
    float bt0 = beta[lane],  bt1 = beta[lane + 32],  bt2 = beta[lane + 64],  bt3 = beta[lane + 96];
    #pragma unroll
    for (int i = 0; i < 4; i++) {
        int r = warp * 4 + i;
        if (r < nrows) {  // warp-uniform
            const float* zr = Ys + r * HID;
            float v0 = zr[lane], v1 = zr[lane + 32], v2 = zr[lane + 64], v3 = zr[lane + 96];
            float s = v0 + v1 + v2 + v3;
            float q = fmaf(v0, v0, fmaf(v1, v1, fmaf(v2, v2, v3 * v3)));
            #pragma unroll
            for (int o = 16; o > 0; o >>= 1) {
                s += __shfl_xor_sync(0xffffffffu, s, o);
                q += __shfl_xor_sync(0xffffffffu, q, o);
            }
            float mean = s * (1.0f / HID);
            float var  = q * (1.0f / HID) - mean * mean;
            float rstd = rsqrtf(var + 1e-5f);
            int v = base + r;
            const float* xr = Xb + (size_t)v * HID;
            float* xo = Xob + (size_t)v * HID;
            xo[lane]      = fmaxf((v0 - mean) * rstd * gm0 + bt0, 0.0f) + xr[lane];
            xo[lane + 32] = fmaxf((v1 - mean) * rstd * gm1 + bt1, 0.0f) + xr[lane + 32];
            xo[lane + 64] = fmaxf((v2 - mean) * rstd * gm2 + bt2, 0.0f) + xr[lane + 64];
            xo[lane + 96] = fmaxf((v3 - mean) * rstd * gm3 + bt3, 0.0f) + xr[lane + 96];
        }
    }
}

// ---------------------------------------------------------------------------
// out = x @ Wout + bout  (x is in g_X0 after 4 layers)
// smem: Ws[128][64] (32KB) + Xs[32][128] (16KB)
// ---------------------------------------------------------------------------
__global__ __launch_bounds__(256) void out_kernel(
    const float* __restrict__ Wout, const float* __restrict__ bout,
    float* __restrict__ out)
{
    extern __shared__ float sm[];
    float* Ws = sm;                   // [128][64]
    float* Xs = sm + HID * OUTD;      // [32][128]
    const int tid  = threadIdx.x;
    const int b    = blockIdx.x / NTILES;
    const int tile = blockIdx.x % NTILES;
    const int base = tile * ROWS;
    const int nrows = min(ROWS, NN - base);
    const float* Xb = g_X0 + (size_t)b * NN * HID;

    {
        const float4* src = (const float4*)Wout;
        float4* dst = (float4*)Ws;
        #pragma unroll
        for (int i = 0; i < 8; i++) dst[tid + 256 * i] = src[tid + 256 * i];
    }
    #pragma unroll
    for (int s = 0; s < 4; s++) {
        int idx = tid + 256 * s;
        int r = idx >> 5;
        int cg = idx & 31;
        if (r < nrows)
            ((float4*)Xs)[idx] = ((const float4*)Xb)[(size_t)(base + r) * 32 + cg];
    }
    __syncthreads();

    const int node = tid >> 3;             // 32 nodes
    const int c0 = (tid & 7) << 3;         // 8 output cols per thread
    float acc[8];
    #pragma unroll
    for (int j = 0; j < 8; j++) acc[j] = 0.0f;

    const float* Xp = Xs + node * HID;
    const float* Wp = Ws + c0;
    #pragma unroll 2
    for (int k0 = 0; k0 < HID; k0 += 4) {
        float4 xv = *(const float4*)(Xp + k0);
        #pragma unroll
        for (int kk = 0; kk < 4; kk++) {
            float x = f4get(xv, kk);
            float4 wa = *(const float4*)(Wp + (k0 + kk) * OUTD);
            float4 wb = *(const float4*)(Wp + (k0 + kk) * OUTD + 4);
            acc[0] = fmaf(x, wa.x, acc[0]);
            acc[1] = fmaf(x, wa.y, acc[1]);
            acc[2] = fmaf(x, wa.z, acc[2]);
            acc[3] = fmaf(x, wa.w, acc[3]);
            acc[4] = fmaf(x, wb.x, acc[4]);
            acc[5] = fmaf(x, wb.y, acc[5]);
            acc[6] = fmaf(x, wb.z, acc[6]);
            acc[7] = fmaf(x, wb.w, acc[7]);
        }
    }

    if (node < nrows) {
        float4 bo1 = *(const float4*)(bout + c0);
        float4 bo2 = *(const float4*)(bout + c0 + 4);
        float* op = out + ((size_t)b * NN + base + node) * OUTD + c0;
        float4 r1 = make_float4(acc[0] + bo1.x, acc[1] + bo1.y, acc[2] + bo1.z, acc[3] + bo1.w);
        float4 r2 = make_float4(acc[4] + bo2.x, acc[5] + bo2.y, acc[6] + bo2.z, acc[7] + bo2.w);
        *(float4*)op = r1;
        *(float4*)(op + 4) = r2;
    }
}

// ---------------------------------------------------------------------------
extern "C" void kernel_launch(void* const* d_in, const int* in_sizes, int n_in,
                              void* d_out, int out_size) {
    const int*   grids = (const int*)d_in[0];
    // d_in[1] = edge_index: graph is a fixed 30x30 4-connected grid; unused.
    const float* Win   = (const float*)d_in[2];
    const float* bin   = (const float*)d_in[3];
    const float* Wg    = (const float*)d_in[4];
    const float* bg    = (const float*)d_in[5];
    const float* gamma = (const float*)d_in[6];
    const float* beta  = (const float*)d_in[7];
    const float* Wout  = (const float*)d_in[8];
    const float* bout  = (const float*)d_in[9];
    float* out = (float*)d_out;
    (void)in_sizes; (void)n_in; (void)out_size;

    const int layer_smem = (HID * HID + ROWS * HID) * 4;   // 81920
    const int out_smem   = (HID * OUTD + ROWS * HID) * 4;  // 49152
    cudaFuncSetAttribute((const void*)layer_kernel,
                         cudaFuncAttributeMaxDynamicSharedMemorySize, layer_smem);
    cudaFuncSetAttribute((const void*)out_kernel,
                         cudaFuncAttributeMaxDynamicSharedMemorySize, out_smem);

    encode_kernel<<<(NB * NN * 32) / 256, 256>>>(grids, Win, bin);
    for (int i = 0; i < 4; i++) {
        layer_kernel<<<NB * NTILES, 256, layer_smem>>>(
            i & 1, Wg + (size_t)i * HID * HID, bg + i * HID,
            gamma + i * HID, beta + i * HID);
    }
    out_kernel<<<NB * NTILES, 256, out_smem>>>(Wout, bout, out);
}

// round 2
// speedup vs baseline: 1.3091x; 1.3091x over previous
#include <cuda_runtime.h>

#define NB   512
#define GH   30
#define GW   30
#define NN   900
#define HID  128
#define OUTD 64
#define LROWS 64
#define LNT   15   // ceil(900/64)
#define ONT   15

// Ping-pong activation buffers (scratch; __device__ globals per allocation rules)
__device__ float g_X0[(size_t)NB * NN * HID];
__device__ float g_X1[(size_t)NB * NN * HID];

typedef unsigned long long ull;

__device__ __forceinline__ float dinv_rc(int rp, int cp) {
    int d = 1 + (rp > 0) + (rp < GH - 1) + (cp > 0) + (cp < GW - 1);
    return rsqrtf((float)d);
}
__device__ __forceinline__ float f4get(const float4& v, int i) {
    return i == 0 ? v.x : i == 1 ? v.y : i == 2 ? v.z : v.w;
}
// Broadcast one float into both lanes of an f32x2 package.
__device__ __forceinline__ ull pack2(float a) {
    ull r; asm("mov.b64 %0, {%1, %1};" : "=l"(r) : "f"(a)); return r;
}
// d = a * b + d on packed f32x2 (Blackwell FFMA2; 2 FMA per instruction)
__device__ __forceinline__ void fma2(ull& d, ull a, ull b) {
    asm("fma.rn.f32x2 %0, %1, %2, %0;" : "+l"(d) : "l"(a), "l"(b));
}
__device__ __forceinline__ float2 unpack2(ull v) {
    float x, y; asm("mov.b64 {%0, %1}, %2;" : "=f"(x), "=f"(y) : "l"(v));
    return make_float2(x, y);
}

// ---------------------------------------------------------------------------
// x0 = relu(onehot(color)@Win + pr*Win[10] + pc*Win[11] + bin), Win in smem
// ---------------------------------------------------------------------------
__global__ __launch_bounds__(256) void encode_kernel(
    const int* __restrict__ grids, const float* __restrict__ Win,
    const float* __restrict__ bin)
{
    __shared__ float4 sW[12 * 32];
    __shared__ float4 sB[32];
    const int tid = threadIdx.x;
    for (int i = tid; i < 384; i += 256) sW[i] = ((const float4*)Win)[i];
    if (tid < 32) sB[tid] = ((const float4*)bin)[tid];
    __syncthreads();

    long long idx = (long long)blockIdx.x * 256 + tid;   // (bn, cg); 8 nodes/CTA
    int cg = (int)(idx & 31);
    long long bn = idx >> 5;
    int n = (int)(bn % NN);
    int color = grids[bn];
    float pr = (float)(n / GW) * (1.0f / (GH - 1));
    float pc = (float)(n % GW) * (1.0f / (GW - 1));
    float4 wc = sW[color * 32 + cg];
    float4 wr = sW[10 * 32 + cg];
    float4 wp = sW[11 * 32 + cg];
    float4 bb = sB[cg];
    float4 o;
    o.x = fmaxf(fmaf(pc, wp.x, fmaf(pr, wr.x, wc.x + bb.x)), 0.0f);
    o.y = fmaxf(fmaf(pc, wp.y, fmaf(pr, wr.y, wc.y + bb.y)), 0.0f);
    o.z = fmaxf(fmaf(pc, wp.z, fmaf(pr, wr.z, wc.z + bb.z)), 0.0f);
    o.w = fmaxf(fmaf(pc, wp.w, fmaf(pr, wr.w, wc.w + bb.w)), 0.0f);
    ((float4*)g_X0)[idx] = o;
}

// ---------------------------------------------------------------------------
// One GCN layer, fused:  y = A_hat@x (stencil) -> z = y@Wg + bg
//                        x_new = relu(LN(z)*gamma+beta) + x
// CTA = (batch, 64-node tile), 256 threads, 8x4 register tiles, f32x2 FMA.
// smem: Ws[128][128] (64KB) + Ys[64][128] (32KB)
// ---------------------------------------------------------------------------
__global__ __launch_bounds__(256, 2) void layer_kernel(
    int flip,
    const float* __restrict__ Wg, const float* __restrict__ bg,
    const float* __restrict__ gamma, const float* __restrict__ beta)
{
    extern __shared__ float sm[];
    float* Ws = sm;                 // [128][128]
    float* Ys = sm + HID * HID;     // [64][128]

    const float* Xin  = flip ? g_X1 : g_X0;
    float*       Xout = flip ? g_X0 : g_X1;

    const int tid  = threadIdx.x;
    const int b    = blockIdx.x / LNT;
    const int tile = blockIdx.x % LNT;
    const int base = tile * LROWS;
    const int nrows = min(LROWS, NN - base);
    const float* Xb = Xin + (size_t)b * NN * HID;
    float*       Xob = Xout + (size_t)b * NN * HID;

    // --- stage Wg in smem (coalesced float4) ---
    {
        const float4* src = (const float4*)Wg;
        float4* dst = (float4*)Ws;
        #pragma unroll
        for (int i = 0; i < 16; i++) dst[tid + 256 * i] = src[tid + 256 * i];
    }

    // --- stencil: Ys[r][:] = sum_u coef(u,v) * x[u][:] ---
    #pragma unroll
    for (int s = 0; s < 8; s++) {
        int idx = tid + 256 * s;          // r*32 + cg
        int r = idx >> 5;
        int cg = idx & 31;
        if (r < nrows) {
            int v = base + r;
            int rp = v / GW;
            int cp = v - rp * GW;
            const float4* X4 = (const float4*)Xb;
            float cv = dinv_rc(rp, cp);
            float4 xs = X4[(size_t)v * 32 + cg];
            float ax = cv * xs.x, ay = cv * xs.y, az = cv * xs.z, aw = cv * xs.w;
            if (rp > 0) {
                float cu = dinv_rc(rp - 1, cp);
                float4 t = X4[(size_t)(v - GW) * 32 + cg];
                ax = fmaf(cu, t.x, ax); ay = fmaf(cu, t.y, ay);
                az = fmaf(cu, t.z, az); aw = fmaf(cu, t.w, aw);
            }
            if (rp < GH - 1) {
                float cu = dinv_rc(rp + 1, cp);
                float4 t = X4[(size_t)(v + GW) * 32 + cg];
                ax = fmaf(cu, t.x, ax); ay = fmaf(cu, t.y, ay);
                az = fmaf(cu, t.z, az); aw = fmaf(cu, t.w, aw);
            }
            if (cp > 0) {
                float cu = dinv_rc(rp, cp - 1);
                float4 t = X4[(size_t)(v - 1) * 32 + cg];
                ax = fmaf(cu, t.x, ax); ay = fmaf(cu, t.y, ay);
                az = fmaf(cu, t.z, az); aw = fmaf(cu, t.w, aw);
            }
            if (cp < GW - 1) {
                float cu = dinv_rc(rp, cp + 1);
                float4 t = X4[(size_t)(v + 1) * 32 + cg];
                ax = fmaf(cu, t.x, ax); ay = fmaf(cu, t.y, ay);
                az = fmaf(cu, t.z, az); aw = fmaf(cu, t.w, aw);
            }
            ((float4*)Ys)[idx] = make_float4(cv * ax, cv * ay, cv * az, cv * aw);
        }
    }
    __syncthreads();

    // --- GEMM: z[64][128] = Ys @ Ws ; thread = 8 rows x 4 cols (2 f32x2) ---
    const int cg = tid & 31;   // cols [cg*4, cg*4+4) -> conflict-free W loads
    const int rg = tid >> 5;   // rows [rg*8, rg*8+8) -> broadcast Y loads
    ull acc[8][2];
    #pragma unroll
    for (int i = 0; i < 8; i++) { acc[i][0] = 0ull; acc[i][1] = 0ull; }

    const float* Yp = Ys + rg * 8 * HID;
    #pragma unroll 2
    for (int k0 = 0; k0 < HID; k0 += 4) {
        float4 y[8];
        #pragma unroll
        for (int i = 0; i < 8; i++)
            y[i] = *(const float4*)(Yp + i * HID + k0);
        #pragma unroll
        for (int kk = 0; kk < 4; kk++) {
            // adjacent W cols reinterpret directly as packed f32x2 operands
            ulonglong2 w = *(const ulonglong2*)(Ws + (k0 + kk) * HID + cg * 4);
            #pragma unroll
            for (int i = 0; i < 8; i++) {
                ull yy = pack2(f4get(y[i], kk));
                fma2(acc[i][0], yy, w.x);
                fma2(acc[i][1], yy, w.y);
            }
        }
    }
    __syncthreads();   // all reads of Ys done before overwrite

    // --- z + bias -> Ys ---
    {
        float4 bgv = ((const float4*)bg)[cg];
        #pragma unroll
        for (int i = 0; i < 8; i++) {
            float2 lo = unpack2(acc[i][0]);
            float2 hi = unpack2(acc[i][1]);
            ((float4*)Ys)[(rg * 8 + i) * 32 + cg] =
                make_float4(lo.x + bgv.x, lo.y + bgv.y, hi.x + bgv.z, hi.y + bgv.w);
        }
    }
    __syncthreads();

    // --- LayerNorm + relu + residual: warp w handles rows w*8..w*8+7 ---
    const int lane = tid & 31;
    const int warp = tid >> 5;
    float gm0 = gamma[lane], gm1 = gamma[lane + 32], gm2 = gamma[lane + 64], gm3 = gamma[lane + 96];
    float bt0 = beta[lane],  bt1 = beta[lane + 32],  bt2 = beta[lane + 64],  bt3 = beta[lane + 96];
    #pragma unroll
    for (int i = 0; i < 8; i++) {
        int r = warp * 8 + i;
        if (r < nrows) {  // warp-uniform
            const float* zr = Ys + r * HID;
            float v0 = zr[lane], v1 = zr[lane + 32], v2 = zr[lane + 64], v3 = zr[lane + 96];
            float s = v0 + v1 + v2 + v3;
            float q = fmaf(v0, v0, fmaf(v1, v1, fmaf(v2, v2, v3 * v3)));
            #pragma unroll
            for (int o = 16; o > 0; o >>= 1) {
                s += __shfl_xor_sync(0xffffffffu, s, o);
                q += __shfl_xor_sync(0xffffffffu, q, o);
            }
            float mean = s * (1.0f / HID);
            float var  = q * (1.0f / HID) - mean * mean;
            float rstd = rsqrtf(var + 1e-5f);
            int v = base + r;
            const float* xr = Xb + (size_t)v * HID;
            float* xo = Xob + (size_t)v * HID;
            xo[lane]      = fmaxf((v0 - mean) * rstd * gm0 + bt0, 0.0f) + xr[lane];
            xo[lane + 32] = fmaxf((v1 - mean) * rstd * gm1 + bt1, 0.0f) + xr[lane + 32];
            xo[lane + 64] = fmaxf((v2 - mean) * rstd * gm2 + bt2, 0.0f) + xr[lane + 64];
            xo[lane + 96] = fmaxf((v3 - mean) * rstd * gm3 + bt3, 0.0f) + xr[lane + 96];
        }
    }
}

// ---------------------------------------------------------------------------
// out = x @ Wout + bout  (x in g_X0 after 4 layers)
// CTA = (batch, 64-node tile), 256 threads, 4x4 register tiles, f32x2 FMA.
// smem: Ws[128][64] (32KB) + Xs[64][128] (32KB)
// ---------------------------------------------------------------------------
__global__ __launch_bounds__(256) void out_kernel(
    const float* __restrict__ Wout, const float* __restrict__ bout,
    float* __restrict__ out)
{
    extern __shared__ float sm[];
    float* Ws = sm;                   // [128][64]
    float* Xs = sm + HID * OUTD;      // [64][128]
    const int tid  = threadIdx.x;
    const int b    = blockIdx.x / ONT;
    const int tile = blockIdx.x % ONT;
    const int base = tile * LROWS;
    const int nrows = min(LROWS, NN - base);
    const float* Xb = g_X0 + (size_t)b * NN * HID;

    {
        const float4* src = (const float4*)Wout;
        float4* dst = (float4*)Ws;
        #pragma unroll
        for (int i = 0; i < 8; i++) dst[tid + 256 * i] = src[tid + 256 * i];
    }
    #pragma unroll
    for (int s = 0; s < 8; s++) {
        int idx = tid + 256 * s;
        int r = idx >> 5;
        int cg = idx & 31;
        if (r < nrows)
            ((float4*)Xs)[idx] = ((const float4*)Xb)[(size_t)(base + r) * 32 + cg];
    }
    __syncthreads();

    const int cg = tid & 15;    // cols [cg*4, cg*4+4)
    const int rg = tid >> 4;    // rows [rg*4, rg*4+4)
    ull acc[4][2];
    #pragma unroll
    for (int i = 0; i < 4; i++) { acc[i][0] = 0ull; acc[i][1] = 0ull; }

    const float* Xp = Xs + rg * 4 * HID;
    #pragma unroll 2
    for (int k0 = 0; k0 < HID; k0 += 4) {
        float4 x[4];
        #pragma unroll
        for (int i = 0; i < 4; i++)
            x[i] = *(const float4*)(Xp + i * HID + k0);
        #pragma unroll
        for (int kk = 0; kk < 4; kk++) {
            ulonglong2 w = *(const ulonglong2*)(Ws + (k0 + kk) * OUTD + cg * 4);
            #pragma unroll
            for (int i = 0; i < 4; i++) {
                ull xx = pack2(f4get(x[i], kk));
                fma2(acc[i][0], xx, w.x);
                fma2(acc[i][1], xx, w.y);
            }
        }
    }

    float4 bo = ((const float4*)bout)[cg];
    #pragma unroll
    for (int i = 0; i < 4; i++) {
        int r = rg * 4 + i;
        if (r < nrows) {
            float2 lo = unpack2(acc[i][0]);
            float2 hi = unpack2(acc[i][1]);
            float4 v = make_float4(lo.x + bo.x, lo.y + bo.y, hi.x + bo.z, hi.y + bo.w);
            *(float4*)(out + ((size_t)b * NN + base + r) * OUTD + cg * 4) = v;
        }
    }
}

// ---------------------------------------------------------------------------
extern "C" void kernel_launch(void* const* d_in, const int* in_sizes, int n_in,
                              void* d_out, int out_size) {
    const int*   grids = (const int*)d_in[0];
    // d_in[1] = edge_index: fixed 30x30 4-connected grid; computed analytically.
    const float* Win   = (const float*)d_in[2];
    const float* bin   = (const float*)d_in[3];
    const float* Wg    = (const float*)d_in[4];
    const float* bg    = (const float*)d_in[5];
    const float* gamma = (const float*)d_in[6];
    const float* beta  = (const float*)d_in[7];
    const float* Wout  = (const float*)d_in[8];
    const float* bout  = (const float*)d_in[9];
    float* out = (float*)d_out;
    (void)in_sizes; (void)n_in; (void)out_size;

    const int layer_smem = (HID * HID + LROWS * HID) * 4;   // 98304
    const int out_smem   = (HID * OUTD + LROWS * HID) * 4;  // 65536
    cudaFuncSetAttribute((const void*)layer_kernel,
                         cudaFuncAttributeMaxDynamicSharedMemorySize, layer_smem);
    cudaFuncSetAttribute((const void*)out_kernel,
                         cudaFuncAttributeMaxDynamicSharedMemorySize, out_smem);

    encode_kernel<<<(NB * NN * 32) / 256, 256>>>(grids, Win, bin);
    for (int i = 0; i < 4; i++) {
        layer_kernel<<<NB * LNT, 256, layer_smem>>>(
            i & 1, Wg + (size_t)i * HID * HID, bg + i * HID,
            gamma + i * HID, beta + i * HID);
    }
    out_kernel<<<NB * ONT, 256, out_smem>>>(Wout, bout, out);
}